// round 1
// baseline (speedup 1.0000x reference)
#include <cuda_runtime.h>
#include <cstdint>

// ---------------------------------------------------------------------------
// LightOnOCR patch merger: 2x2 spatial unfold (channel-major) + Linear(4096->1024)
// Strategy:
//   out[r, n] = sum_{off in 0..3} sum_{dd} feat[tok(r,off), dd] * W[n, dd*4+off]
// i.e. 4 accumulated K=1024 GEMMs where A rows are gathered token rows and
// B = reordered weight g_Wr[off][n][dd] (contiguous dd). TF32 mma.sync, fp32 accum.
// Shapes are fixed by the dataset: M=11955 merged rows, N=1024, K=4*1024.
// ---------------------------------------------------------------------------

#define M_TOTAL 11955

// 16 MB reordered weight scratch (static device allocation — allowed).
static __device__ unsigned g_Wr[4u * 1024u * 1024u];

// Hardcoded image table (from IMAGE_SIZES; PATCH=14, MERGE=2):
// h_patches = {110,80,64,110,90,52}, w_patches = {88,110,90,110,64,110}
__constant__ int c_moff[7] = {0, 2420, 4620, 6060, 9085, 10525, 11955}; // merged row offsets
__constant__ int c_toff[6] = {0, 9680, 18480, 24240, 36340, 42100};     // token offsets
__constant__ int c_wm[6]   = {44, 55, 45, 55, 32, 55};                  // merged width (w/2)
__constant__ int c_w[6]    = {88, 110, 90, 110, 64, 110};               // patch-grid width

__device__ __forceinline__ unsigned f2tf(float f) {
    unsigned u;
    asm("cvt.rna.tf32.f32 %0, %1;" : "=r"(u) : "f"(f));
    return u;
}

// Reorder weight [1024, 4096] -> g_Wr[off][n][dd] (tf32-rounded bits).
// One thread per (n, dd): float4 read (4 consecutive cols = 4 offs), 4 coalesced writes.
__global__ void reorder_w_kernel(const float* __restrict__ w) {
    int id = blockIdx.x * 256 + threadIdx.x;      // 0 .. 1024*1024-1
    int n  = id >> 10;
    int dd = id & 1023;
    float4 v = *reinterpret_cast<const float4*>(w + (size_t)n * 4096 + (dd << 2));
    g_Wr[0u * 1048576u + (n << 10) + dd] = f2tf(v.x);
    g_Wr[1u * 1048576u + (n << 10) + dd] = f2tf(v.y);
    g_Wr[2u * 1048576u + (n << 10) + dd] = f2tf(v.z);
    g_Wr[3u * 1048576u + (n << 10) + dd] = f2tf(v.w);
}

// Fused gather + TF32 GEMM. Block tile 128(M) x 128(N) x 32(K), 8 warps of 32x64.
__global__ __launch_bounds__(256, 2) void merger_gemm(
    const float* __restrict__ feat, float* __restrict__ out)
{
    __shared__ unsigned sA[128][36];   // [m][k], pad 4 -> conflict-free frag loads
    __shared__ unsigned sB[128][36];   // [n][k]
    __shared__ int sTok[128];
    __shared__ int sWd[128];

    const int t  = threadIdx.x;
    const int m0 = blockIdx.y << 7;
    const int n0 = blockIdx.x << 7;

    // Per-block row map: merged row -> (base token t00, patch-grid width)
    if (t < 128) {
        int r = m0 + t;
        if (r > M_TOTAL - 1) r = M_TOTAL - 1;    // clamp for safe loads; store guarded
        int img = 0;
        #pragma unroll
        for (int i = 1; i < 6; i++) img += (r >= c_moff[i]);
        int local = r - c_moff[img];
        int wm = c_wm[img];
        int br = local / wm;
        int bc = local - br * wm;
        sTok[t] = c_toff[img] + (br << 1) * c_w[img] + (bc << 1);
        sWd[t]  = c_w[img];
    }
    __syncthreads();

    const int warp = t >> 5;
    const int lane = t & 31;
    const int wr = warp >> 1;   // 0..3 (M, 32 rows each)
    const int wc = warp & 1;    // 0..1 (N, 64 cols each)
    const int tg = lane >> 2;   // groupID 0..7
    const int t4 = lane & 3;    // threadID-in-group

    float acc[2][8][4];
    #pragma unroll
    for (int mf = 0; mf < 2; mf++)
        #pragma unroll
        for (int nf = 0; nf < 8; nf++)
            #pragma unroll
            for (int i = 0; i < 4; i++) acc[mf][nf][i] = 0.0f;

    for (int kt = 0; kt < 128; kt++) {
        const int koff = kt >> 5;                 // which of the 4 unfold offsets
        const int kh = koff >> 1, kw = koff & 1;
        const int dd0 = (kt & 31) << 5;           // feature offset within 1024 chunk

        // Load A tile: 128 rows x 32 k (gathered token rows), tf32-converted.
        #pragma unroll
        for (int j = 0; j < 4; j++) {
            int idx = t + (j << 8);
            int row = idx >> 3, c4 = idx & 7;
            int token = sTok[row] + kh * sWd[row] + kw;
            float4 v = *reinterpret_cast<const float4*>(
                feat + (size_t)token * 1024 + dd0 + (c4 << 2));
            uint4 a;
            a.x = f2tf(v.x); a.y = f2tf(v.y); a.z = f2tf(v.z); a.w = f2tf(v.w);
            *reinterpret_cast<uint4*>(&sA[row][c4 << 2]) = a;
        }
        // Load B tile: 128 n-rows x 32 k from reordered weight (already tf32).
        #pragma unroll
        for (int j = 0; j < 4; j++) {
            int idx = t + (j << 8);
            int row = idx >> 3, c4 = idx & 7;
            uint4 v = *reinterpret_cast<const uint4*>(
                g_Wr + ((size_t)koff << 20) + ((size_t)(n0 + row) << 10) + dd0 + (c4 << 2));
            *reinterpret_cast<uint4*>(&sB[row][c4 << 2]) = v;
        }
        __syncthreads();

        #pragma unroll
        for (int ks = 0; ks < 4; ks++) {
            const int k0 = ks << 3;
            unsigned a[2][4];
            #pragma unroll
            for (int mf = 0; mf < 2; mf++) {
                int mrow = (wr << 5) + (mf << 4) + tg;
                a[mf][0] = sA[mrow][k0 + t4];
                a[mf][1] = sA[mrow + 8][k0 + t4];
                a[mf][2] = sA[mrow][k0 + t4 + 4];
                a[mf][3] = sA[mrow + 8][k0 + t4 + 4];
            }
            #pragma unroll
            for (int nf = 0; nf < 8; nf++) {
                int nrow = (wc << 6) + (nf << 3) + tg;
                unsigned b0 = sB[nrow][k0 + t4];
                unsigned b1 = sB[nrow][k0 + t4 + 4];
                #pragma unroll
                for (int mf = 0; mf < 2; mf++) {
                    asm volatile(
                        "mma.sync.aligned.m16n8k8.row.col.f32.tf32.tf32.f32 "
                        "{%0,%1,%2,%3}, {%4,%5,%6,%7}, {%8,%9}, {%0,%1,%2,%3};"
                        : "+f"(acc[mf][nf][0]), "+f"(acc[mf][nf][1]),
                          "+f"(acc[mf][nf][2]), "+f"(acc[mf][nf][3])
                        : "r"(a[mf][0]), "r"(a[mf][1]), "r"(a[mf][2]), "r"(a[mf][3]),
                          "r"(b0), "r"(b1));
                }
            }
        }
        __syncthreads();
    }

    // Epilogue: c0/c1 -> (row, 2*t4 / +1), c2/c3 -> (row+8, ...)
    #pragma unroll
    for (int mf = 0; mf < 2; mf++) {
        int rbase = m0 + (wr << 5) + (mf << 4) + tg;
        #pragma unroll
        for (int nf = 0; nf < 8; nf++) {
            int col = n0 + (wc << 6) + (nf << 3) + (t4 << 1);
            if (rbase < M_TOTAL) {
                float2 v = make_float2(acc[mf][nf][0], acc[mf][nf][1]);
                *reinterpret_cast<float2*>(out + (size_t)rbase * 1024 + col) = v;
            }
            if (rbase + 8 < M_TOTAL) {
                float2 v = make_float2(acc[mf][nf][2], acc[mf][nf][3]);
                *reinterpret_cast<float2*>(out + (size_t)(rbase + 8) * 1024 + col) = v;
            }
        }
    }
}

extern "C" void kernel_launch(void* const* d_in, const int* in_sizes, int n_in,
                              void* d_out, int out_size)
{
    const float* feat   = (const float*)d_in[0];   // [47820, 1024] fp32
    const float* weight = (const float*)d_in[1];   // [1024, 4096] fp32
    float* out = (float*)d_out;                    // [11955, 1024] fp32
    (void)in_sizes; (void)n_in; (void)out_size;    // shapes fixed by dataset

    reorder_w_kernel<<<4096, 256>>>(weight);
    merger_gemm<<<dim3(8, 94), 256>>>(feat, out);
}

// round 4
// speedup vs baseline: 1.2142x; 1.2142x over previous
#include <cuda_runtime.h>
#include <cstdint>

// ---------------------------------------------------------------------------
// LightOnOCR patch merger (sm_103 via compute_103-safe path):
//   out[r,n] = sum_{off<4} sum_{dd<1024} feat[tok(r,off),dd] * Wr[off][n][dd]
// Fused gather + TF32 mma.sync GEMM, M=11955, N=1024, K=4096.
// CTA tile 128x128, 4 warps of 64x64, K-chunk 32, 3-stage cp.async pipeline.
// ---------------------------------------------------------------------------

#define M_TOTAL 11955
#define STAGE_BYTES 36864            // A: 128x36 words (18432B) + B: 128x36 words
#define SMEM_DYN (3 * STAGE_BYTES)   // 110592 B

static __device__ unsigned g_Wr[4u * 1024u * 1024u];   // [off][n][dd], tf32 bits

// Image table (IMAGE_SIZES, PATCH=14, MERGE=2)
__constant__ int c_moff[7] = {0, 2420, 4620, 6060, 9085, 10525, 11955};
__constant__ int c_toff[6] = {0, 9680, 18480, 24240, 36340, 42100};
__constant__ int c_wm[6]   = {44, 55, 45, 55, 32, 55};
__constant__ int c_w[6]    = {88, 110, 90, 110, 64, 110};

__device__ __forceinline__ unsigned f2tf(float f) {
    unsigned u;
    asm("cvt.rna.tf32.f32 %0, %1;" : "=r"(u) : "f"(f));
    return u;
}
__device__ __forceinline__ uint32_t s2u(const void* p) {
    uint32_t a;
    asm("{ .reg .u64 t; cvta.to.shared.u64 t, %1; cvt.u32.u64 %0, t; }" : "=r"(a) : "l"(p));
    return a;
}
__device__ __forceinline__ void cp16(uint32_t dst, const void* src) {
    asm volatile("cp.async.cg.shared.global [%0], [%1], 16;" :: "r"(dst), "l"(src) : "memory");
}

// Weight reorder: [1024, 4096] -> g_Wr[off][n][dd], tf32-rounded (RNA).
__global__ void reorder_w_kernel(const float* __restrict__ w) {
    int id = blockIdx.x * 256 + threadIdx.x;
    int n = id >> 10, dd = id & 1023;
    float4 v = *reinterpret_cast<const float4*>(w + (size_t)n * 4096 + (dd << 2));
    g_Wr[0u * 1048576u + (n << 10) + dd] = f2tf(v.x);
    g_Wr[1u * 1048576u + (n << 10) + dd] = f2tf(v.y);
    g_Wr[2u * 1048576u + (n << 10) + dd] = f2tf(v.z);
    g_Wr[3u * 1048576u + (n << 10) + dd] = f2tf(v.w);
}

__global__ __launch_bounds__(128, 2) void merger_gemm(
    const float* __restrict__ feat, float* __restrict__ out)
{
    extern __shared__ char smem[];
    const int t = threadIdx.x, wid = t >> 5, lane = t & 31;
    const int m0 = blockIdx.y << 7, n0 = blockIdx.x << 7;

    // Per-thread row map: this thread fills merged row (m0 + t) of the A tile.
    int tok0, wd;
    {
        int r = m0 + t;
        if (r > M_TOTAL - 1) r = M_TOTAL - 1;   // clamp loads; stores guarded
        int img = 0;
        #pragma unroll
        for (int i = 1; i < 6; i++) img += (r >= c_moff[i]);
        int local = r - c_moff[img];
        int wm = c_wm[img];
        int br = local / wm, bc = local - br * wm;
        tok0 = c_toff[img] + (br << 1) * c_w[img] + (bc << 1);
        wd   = c_w[img];
    }

    const uint32_t sbase = s2u(smem);
    const uint32_t dArow = t * 144;             // row stride 36 words = 144 B
    const unsigned* wB = g_Wr + ((size_t)(n0 + t) << 10);

    // Fill stage for K-chunk kc (32 floats per row): A gathered rows + B rows.
    auto fill = [&](int kc) {
        const int s = kc % 3;
        const int koff = kc >> 5;               // unfold offset 0..3
        const int dd0 = (kc & 31) << 5;
        const int kh = koff >> 1, kw = koff & 1;
        const float* srcA = feat + (size_t)(tok0 + kh * wd + kw) * 1024 + dd0;
        const unsigned* srcB = wB + ((size_t)koff << 20) + dd0;
        const uint32_t dA = sbase + s * STAGE_BYTES + dArow;
        const uint32_t dB = dA + 18432;
        #pragma unroll
        for (int cc = 0; cc < 8; cc++) {
            cp16(dA + cc * 16, srcA + cc * 4);
            cp16(dB + cc * 16, srcB + cc * 4);
        }
        asm volatile("cp.async.commit_group;" ::: "memory");
    };

    const int tg = lane >> 2, t4 = lane & 3;
    const int wr = wid >> 1, wc = wid & 1;      // warp grid 2x2, 64x64 each

    float acc[4][8][4];
    #pragma unroll
    for (int mf = 0; mf < 4; mf++)
        #pragma unroll
        for (int nf = 0; nf < 8; nf++)
            #pragma unroll
            for (int i = 0; i < 4; i++) acc[mf][nf][i] = 0.0f;

    fill(0);
    fill(1);

    for (int kt = 0; kt < 128; kt++) {
        if (kt < 126) asm volatile("cp.async.wait_group 1;" ::: "memory");
        else          asm volatile("cp.async.wait_group 0;" ::: "memory");
        __syncthreads();
        if (kt + 2 < 128) fill(kt + 2);

        const unsigned* sA = reinterpret_cast<const unsigned*>(smem + (kt % 3) * STAGE_BYTES);
        const unsigned* sB = sA + 4608;         // 18432 B
        #pragma unroll
        for (int ks = 0; ks < 4; ks++) {
            const int k0 = ks << 3;
            unsigned a[4][4];
            #pragma unroll
            for (int mf = 0; mf < 4; mf++) {
                const int mrow = (wr << 6) + (mf << 4) + tg;
                const unsigned* p0 = sA + mrow * 36 + k0 + t4;
                const unsigned* p8 = p0 + 8 * 36;
                a[mf][0] = f2tf(__uint_as_float(p0[0]));
                a[mf][1] = f2tf(__uint_as_float(p8[0]));
                a[mf][2] = f2tf(__uint_as_float(p0[4]));
                a[mf][3] = f2tf(__uint_as_float(p8[4]));
            }
            #pragma unroll
            for (int nf = 0; nf < 8; nf++) {
                const int nrow = (wc << 6) + (nf << 3) + tg;
                unsigned b0 = sB[nrow * 36 + k0 + t4];
                unsigned b1 = sB[nrow * 36 + k0 + t4 + 4];
                #pragma unroll
                for (int mf = 0; mf < 4; mf++) {
                    asm volatile(
                        "mma.sync.aligned.m16n8k8.row.col.f32.tf32.tf32.f32 "
                        "{%0,%1,%2,%3}, {%4,%5,%6,%7}, {%8,%9}, {%0,%1,%2,%3};"
                        : "+f"(acc[mf][nf][0]), "+f"(acc[mf][nf][1]),
                          "+f"(acc[mf][nf][2]), "+f"(acc[mf][nf][3])
                        : "r"(a[mf][0]), "r"(a[mf][1]), "r"(a[mf][2]), "r"(a[mf][3]),
                          "r"(b0), "r"(b1));
                }
            }
        }
        __syncthreads();
    }

    // Epilogue
    #pragma unroll
    for (int mf = 0; mf < 4; mf++) {
        const int row0 = m0 + (wr << 6) + (mf << 4) + tg;
        #pragma unroll
        for (int nf = 0; nf < 8; nf++) {
            const int col = n0 + (wc << 6) + (nf << 3) + (t4 << 1);
            if (row0 < M_TOTAL)
                *reinterpret_cast<float2*>(out + (size_t)row0 * 1024 + col) =
                    make_float2(acc[mf][nf][0], acc[mf][nf][1]);
            if (row0 + 8 < M_TOTAL)
                *reinterpret_cast<float2*>(out + (size_t)(row0 + 8) * 1024 + col) =
                    make_float2(acc[mf][nf][2], acc[mf][nf][3]);
        }
    }
}

extern "C" void kernel_launch(void* const* d_in, const int* in_sizes, int n_in,
                              void* d_out, int out_size)
{
    const float* feat   = (const float*)d_in[0];   // [47820, 1024] fp32
    const float* weight = (const float*)d_in[1];   // [1024, 4096] fp32
    float* out = (float*)d_out;                    // [11955, 1024] fp32
    (void)in_sizes; (void)n_in; (void)out_size;

    cudaFuncSetAttribute(merger_gemm, cudaFuncAttributeMaxDynamicSharedMemorySize, SMEM_DYN);
    reorder_w_kernel<<<4096, 256>>>(weight);
    merger_gemm<<<dim3(8, 94), 128, SMEM_DYN>>>(feat, out);
}

// round 5
// speedup vs baseline: 2.2485x; 1.8518x over previous
#include <cuda_runtime.h>
#include <cstdint>

// ---------------------------------------------------------------------------
// LightOnOCR patch merger: fused 2x2 unfold gather + Linear(4096->1024), TF32
// mma.sync. M=11955, N=1024, K=4096. CTA 128x128, 4 warps (64x64 each),
// K-chunk 32, 4-stage cp.async pipeline, XOR-swizzled smem, coalesced fills.
// ---------------------------------------------------------------------------

#define M_TOTAL 11955
#define STAGE_BYTES 32768            // A 16KB (128 rows x 128B) + B 16KB
#define SMEM_DYN (4 * STAGE_BYTES)   // 131072 B

static __device__ unsigned g_Wr[4u * 1024u * 1024u];   // [off][n][dd], tf32 bits

// Image table (IMAGE_SIZES, PATCH=14, MERGE=2)
__constant__ int c_moff[7] = {0, 2420, 4620, 6060, 9085, 10525, 11955};
__constant__ int c_toff[6] = {0, 9680, 18480, 24240, 36340, 42100};
__constant__ int c_wm[6]   = {44, 55, 45, 55, 32, 55};
__constant__ int c_w[6]    = {88, 110, 90, 110, 64, 110};

__device__ __forceinline__ unsigned f2tf(float f) {
    unsigned u;
    asm("cvt.rna.tf32.f32 %0, %1;" : "=r"(u) : "f"(f));
    return u;
}
__device__ __forceinline__ uint32_t s2u(const void* p) {
    uint32_t a;
    asm("{ .reg .u64 t; cvta.to.shared.u64 t, %1; cvt.u32.u64 %0, t; }" : "=r"(a) : "l"(p));
    return a;
}
__device__ __forceinline__ void cp16(uint32_t dst, const void* src) {
    asm volatile("cp.async.cg.shared.global [%0], [%1], 16;" :: "r"(dst), "l"(src) : "memory");
}

// Weight reorder: [1024, 4096] -> g_Wr[off][n][dd], tf32-rounded (RNA).
__global__ void reorder_w_kernel(const float* __restrict__ w) {
    int id = blockIdx.x * 256 + threadIdx.x;
    int n = id >> 10, dd = id & 1023;
    float4 v = *reinterpret_cast<const float4*>(w + (size_t)n * 4096 + (dd << 2));
    g_Wr[0u * 1048576u + (n << 10) + dd] = f2tf(v.x);
    g_Wr[1u * 1048576u + (n << 10) + dd] = f2tf(v.y);
    g_Wr[2u * 1048576u + (n << 10) + dd] = f2tf(v.z);
    g_Wr[3u * 1048576u + (n << 10) + dd] = f2tf(v.w);
}

__global__ __launch_bounds__(128, 2) void merger_gemm(
    const float* __restrict__ feat, float* __restrict__ out)
{
    extern __shared__ char smem[];
    __shared__ int sTok[128], sWd[128];
    const int t = threadIdx.x, wid = t >> 5, lane = t & 31;
    const int m0 = blockIdx.y << 7, n0 = blockIdx.x << 7;

    // Row map into shared: merged row (m0+i) -> (base token, patch width)
    {
        int r = m0 + t;
        if (r > M_TOTAL - 1) r = M_TOTAL - 1;   // clamp loads; stores guarded
        int img = 0;
        #pragma unroll
        for (int i = 1; i < 6; i++) img += (r >= c_moff[i]);
        int local = r - c_moff[img];
        int wm = c_wm[img];
        int br = local / wm, bc = local - br * wm;
        sTok[t] = c_toff[img] + (br << 1) * c_w[img] + (bc << 1);
        sWd[t]  = c_w[img];
    }
    __syncthreads();

    // Fill mapping: thread handles rows {16j + (t>>3)}, chunk c = t&7 (16B).
    // Warp lanes cover 4 rows x 8 chunks = four full 128B lines (coalesced).
    const int rbase = t >> 3, c = t & 7;
    const uint32_t csw = (uint32_t)(c ^ (rbase & 7)) << 4;   // swizzled chunk byte off
    const uint32_t off0 = (uint32_t)rbase * 128 + csw;
    int tokA[8], wdA[8];
    const unsigned* pB[8];
    #pragma unroll
    for (int j = 0; j < 8; j++) {
        int row = (j << 4) + rbase;
        tokA[j] = sTok[row];
        wdA[j]  = sWd[row];
        pB[j]   = g_Wr + ((size_t)(n0 + row) << 10) + (c << 2);
    }
    const uint32_t sbase = s2u(smem);

    auto fill = [&](int kc) {
        const int s = kc & 3;
        const int koff = kc >> 5;
        const int dd0 = (kc & 31) << 5;
        const int kh = koff >> 1, kw = koff & 1;
        const uint32_t dA = sbase + s * STAGE_BYTES + off0;
        const size_t woff = ((size_t)koff << 20) + dd0;
        #pragma unroll
        for (int j = 0; j < 8; j++) {
            int token = tokA[j] + kh * wdA[j] + kw;
            cp16(dA + (j << 11),
                 feat + (size_t)token * 1024 + dd0 + (c << 2));
            cp16(dA + 16384 + (j << 11), pB[j] + woff);
        }
        asm volatile("cp.async.commit_group;" ::: "memory");
    };

    const int tg = lane >> 2, t4 = lane & 3;
    const int wr = wid >> 1, wc = wid & 1;      // warp grid 2x2, 64x64 tiles

    float acc[4][8][4];
    #pragma unroll
    for (int mf = 0; mf < 4; mf++)
        #pragma unroll
        for (int nf = 0; nf < 8; nf++)
            #pragma unroll
            for (int i = 0; i < 4; i++) acc[mf][nf][i] = 0.0f;

    fill(0); fill(1); fill(2);

    for (int kt = 0; kt < 128; kt++) {
        if (kt < 126)      asm volatile("cp.async.wait_group 2;" ::: "memory");
        else if (kt == 126) asm volatile("cp.async.wait_group 1;" ::: "memory");
        else                asm volatile("cp.async.wait_group 0;" ::: "memory");
        __syncthreads();
        if (kt + 3 < 128) fill(kt + 3);

        const unsigned* sA = reinterpret_cast<const unsigned*>(smem + (kt & 3) * STAGE_BYTES);
        const unsigned* sB = sA + 4096;
        #pragma unroll
        for (int ks = 0; ks < 4; ks++) {
            // swizzled word offsets within a row for k = ks*8 + t4 (+4)
            const int x0 = ((((ks << 1)    ) ^ tg) << 2) + t4;
            const int x1 = ((((ks << 1) + 1) ^ tg) << 2) + t4;
            unsigned a[4][4];
            #pragma unroll
            for (int mf = 0; mf < 4; mf++) {
                const int mrow = (wr << 6) + (mf << 4) + tg;
                const unsigned* p0 = sA + (mrow << 5);
                const unsigned* p8 = p0 + 256;
                a[mf][0] = f2tf(__uint_as_float(p0[x0]));
                a[mf][1] = f2tf(__uint_as_float(p8[x0]));
                a[mf][2] = f2tf(__uint_as_float(p0[x1]));
                a[mf][3] = f2tf(__uint_as_float(p8[x1]));
            }
            #pragma unroll
            for (int nf = 0; nf < 8; nf++) {
                const int nrow = (wc << 6) + (nf << 3) + tg;
                const unsigned* q = sB + (nrow << 5);
                unsigned b0 = q[x0];
                unsigned b1 = q[x1];
                #pragma unroll
                for (int mf = 0; mf < 4; mf++) {
                    asm volatile(
                        "mma.sync.aligned.m16n8k8.row.col.f32.tf32.tf32.f32 "
                        "{%0,%1,%2,%3}, {%4,%5,%6,%7}, {%8,%9}, {%0,%1,%2,%3};"
                        : "+f"(acc[mf][nf][0]), "+f"(acc[mf][nf][1]),
                          "+f"(acc[mf][nf][2]), "+f"(acc[mf][nf][3])
                        : "r"(a[mf][0]), "r"(a[mf][1]), "r"(a[mf][2]), "r"(a[mf][3]),
                          "r"(b0), "r"(b1));
                }
            }
        }
    }

    // Epilogue
    #pragma unroll
    for (int mf = 0; mf < 4; mf++) {
        const int row0 = m0 + (wr << 6) + (mf << 4) + tg;
        #pragma unroll
        for (int nf = 0; nf < 8; nf++) {
            const int col = n0 + (wc << 6) + (nf << 3) + (t4 << 1);
            if (row0 < M_TOTAL)
                *reinterpret_cast<float2*>(out + (size_t)row0 * 1024 + col) =
                    make_float2(acc[mf][nf][0], acc[mf][nf][1]);
            if (row0 + 8 < M_TOTAL)
                *reinterpret_cast<float2*>(out + (size_t)(row0 + 8) * 1024 + col) =
                    make_float2(acc[mf][nf][2], acc[mf][nf][3]);
        }
    }
}

extern "C" void kernel_launch(void* const* d_in, const int* in_sizes, int n_in,
                              void* d_out, int out_size)
{
    const float* feat   = (const float*)d_in[0];   // [47820, 1024] fp32
    const float* weight = (const float*)d_in[1];   // [1024, 4096] fp32
    float* out = (float*)d_out;                    // [11955, 1024] fp32
    (void)in_sizes; (void)n_in; (void)out_size;

    cudaFuncSetAttribute(merger_gemm, cudaFuncAttributeMaxDynamicSharedMemorySize, SMEM_DYN);
    reorder_w_kernel<<<4096, 256>>>(weight);
    merger_gemm<<<dim3(8, 94), 128, SMEM_DYN>>>(feat, out);
}

// round 6
// speedup vs baseline: 2.5795x; 1.1472x over previous
#include <cuda_runtime.h>
#include <cstdint>

// ---------------------------------------------------------------------------
// LightOnOCR patch merger: fused 2x2 unfold gather + Linear(4096->1024), TF32
// mma.sync. M=11955, N=1024, K=4096. CTA 128x128, 4 warps (64x64 each),
// K-chunk 32, 3-stage cp.async pipeline (96KB smem -> 2 CTAs/SM),
// XOR-swizzled smem, coalesced fills.
// ---------------------------------------------------------------------------

#define M_TOTAL 11955
#define STAGE_BYTES 32768            // A 16KB (128 rows x 128B) + B 16KB
#define SMEM_DYN (3 * STAGE_BYTES)   // 98304 B -> 2 CTAs/SM on 228KB

static __device__ unsigned g_Wr[4u * 1024u * 1024u];   // [off][n][dd], tf32 bits

// Image table (IMAGE_SIZES, PATCH=14, MERGE=2)
__constant__ int c_moff[7] = {0, 2420, 4620, 6060, 9085, 10525, 11955};
__constant__ int c_toff[6] = {0, 9680, 18480, 24240, 36340, 42100};
__constant__ int c_wm[6]   = {44, 55, 45, 55, 32, 55};
__constant__ int c_w[6]    = {88, 110, 90, 110, 64, 110};

__device__ __forceinline__ unsigned f2tf(float f) {
    unsigned u;
    asm("cvt.rna.tf32.f32 %0, %1;" : "=r"(u) : "f"(f));
    return u;
}
__device__ __forceinline__ uint32_t s2u(const void* p) {
    uint32_t a;
    asm("{ .reg .u64 t; cvta.to.shared.u64 t, %1; cvt.u32.u64 %0, t; }" : "=r"(a) : "l"(p));
    return a;
}
__device__ __forceinline__ void cp16(uint32_t dst, const void* src) {
    asm volatile("cp.async.cg.shared.global [%0], [%1], 16;" :: "r"(dst), "l"(src) : "memory");
}

// Weight reorder: [1024, 4096] -> g_Wr[off][n][dd], tf32-rounded (RNA).
__global__ void reorder_w_kernel(const float* __restrict__ w) {
    int id = blockIdx.x * 256 + threadIdx.x;
    int n = id >> 10, dd = id & 1023;
    float4 v = *reinterpret_cast<const float4*>(w + (size_t)n * 4096 + (dd << 2));
    g_Wr[0u * 1048576u + (n << 10) + dd] = f2tf(v.x);
    g_Wr[1u * 1048576u + (n << 10) + dd] = f2tf(v.y);
    g_Wr[2u * 1048576u + (n << 10) + dd] = f2tf(v.z);
    g_Wr[3u * 1048576u + (n << 10) + dd] = f2tf(v.w);
}

__global__ __launch_bounds__(128, 2) void merger_gemm(
    const float* __restrict__ feat, float* __restrict__ out)
{
    extern __shared__ char smem[];
    __shared__ int sTok[128], sWd[128];
    const int t = threadIdx.x, wid = t >> 5, lane = t & 31;
    const int m0 = blockIdx.y << 7, n0 = blockIdx.x << 7;

    // Row map into shared: merged row (m0+i) -> (base token, patch width)
    {
        int r = m0 + t;
        if (r > M_TOTAL - 1) r = M_TOTAL - 1;   // clamp loads; stores guarded
        int img = 0;
        #pragma unroll
        for (int i = 1; i < 6; i++) img += (r >= c_moff[i]);
        int local = r - c_moff[img];
        int wm = c_wm[img];
        int br = local / wm, bc = local - br * wm;
        sTok[t] = c_toff[img] + (br << 1) * c_w[img] + (bc << 1);
        sWd[t]  = c_w[img];
    }
    __syncthreads();

    // Fill mapping: thread handles rows {16j + (t>>3)}, chunk c = t&7 (16B).
    // Warp lanes cover 4 rows x 8 chunks = four full 128B lines (coalesced).
    const int rbase = t >> 3, c = t & 7;
    const uint32_t csw = (uint32_t)(c ^ (rbase & 7)) << 4;   // swizzled chunk byte off
    const uint32_t off0 = (uint32_t)rbase * 128 + csw;
    int tokA[8], wdA[8];
    const unsigned* pB[8];
    #pragma unroll
    for (int j = 0; j < 8; j++) {
        int row = (j << 4) + rbase;
        tokA[j] = sTok[row];
        wdA[j]  = sWd[row];
        pB[j]   = g_Wr + ((size_t)(n0 + row) << 10) + (c << 2);
    }
    const uint32_t sbase = s2u(smem);

    auto fill = [&](int kc) {
        const int s = kc % 3;
        const int koff = kc >> 5;
        const int dd0 = (kc & 31) << 5;
        const int kh = koff >> 1, kw = koff & 1;
        const uint32_t dA = sbase + s * STAGE_BYTES + off0;
        const size_t woff = ((size_t)koff << 20) + dd0;
        #pragma unroll
        for (int j = 0; j < 8; j++) {
            int token = tokA[j] + kh * wdA[j] + kw;
            cp16(dA + (j << 11),
                 feat + (size_t)token * 1024 + dd0 + (c << 2));
            cp16(dA + 16384 + (j << 11), pB[j] + woff);
        }
        asm volatile("cp.async.commit_group;" ::: "memory");
    };

    const int tg = lane >> 2, t4 = lane & 3;
    const int wr = wid >> 1, wc = wid & 1;      // warp grid 2x2, 64x64 tiles

    float acc[4][8][4];
    #pragma unroll
    for (int mf = 0; mf < 4; mf++)
        #pragma unroll
        for (int nf = 0; nf < 8; nf++)
            #pragma unroll
            for (int i = 0; i < 4; i++) acc[mf][nf][i] = 0.0f;

    fill(0); fill(1);

    for (int kt = 0; kt < 128; kt++) {
        if (kt < 127) asm volatile("cp.async.wait_group 1;" ::: "memory");
        else          asm volatile("cp.async.wait_group 0;" ::: "memory");
        __syncthreads();
        if (kt + 2 < 128) fill(kt + 2);

        const unsigned* sA = reinterpret_cast<const unsigned*>(smem + (kt % 3) * STAGE_BYTES);
        const unsigned* sB = sA + 4096;
        #pragma unroll
        for (int ks = 0; ks < 4; ks++) {
            // swizzled word offsets within a row for k = ks*8 + t4 (+4)
            const int x0 = ((((ks << 1)    ) ^ tg) << 2) + t4;
            const int x1 = ((((ks << 1) + 1) ^ tg) << 2) + t4;
            unsigned a[4][4];
            #pragma unroll
            for (int mf = 0; mf < 4; mf++) {
                const int mrow = (wr << 6) + (mf << 4) + tg;
                const unsigned* p0 = sA + (mrow << 5);
                const unsigned* p8 = p0 + 256;
                a[mf][0] = f2tf(__uint_as_float(p0[x0]));
                a[mf][1] = f2tf(__uint_as_float(p8[x0]));
                a[mf][2] = f2tf(__uint_as_float(p0[x1]));
                a[mf][3] = f2tf(__uint_as_float(p8[x1]));
            }
            #pragma unroll
            for (int nf = 0; nf < 8; nf++) {
                const int nrow = (wc << 6) + (nf << 3) + tg;
                const unsigned* q = sB + (nrow << 5);
                unsigned b0 = q[x0];
                unsigned b1 = q[x1];
                #pragma unroll
                for (int mf = 0; mf < 4; mf++) {
                    asm volatile(
                        "mma.sync.aligned.m16n8k8.row.col.f32.tf32.tf32.f32 "
                        "{%0,%1,%2,%3}, {%4,%5,%6,%7}, {%8,%9}, {%0,%1,%2,%3};"
                        : "+f"(acc[mf][nf][0]), "+f"(acc[mf][nf][1]),
                          "+f"(acc[mf][nf][2]), "+f"(acc[mf][nf][3])
                        : "r"(a[mf][0]), "r"(a[mf][1]), "r"(a[mf][2]), "r"(a[mf][3]),
                          "r"(b0), "r"(b1));
                }
            }
        }
    }

    // Epilogue
    #pragma unroll
    for (int mf = 0; mf < 4; mf++) {
        const int row0 = m0 + (wr << 6) + (mf << 4) + tg;
        #pragma unroll
        for (int nf = 0; nf < 8; nf++) {
            const int col = n0 + (wc << 6) + (nf << 3) + (t4 << 1);
            if (row0 < M_TOTAL)
                *reinterpret_cast<float2*>(out + (size_t)row0 * 1024 + col) =
                    make_float2(acc[mf][nf][0], acc[mf][nf][1]);
            if (row0 + 8 < M_TOTAL)
                *reinterpret_cast<float2*>(out + (size_t)(row0 + 8) * 1024 + col) =
                    make_float2(acc[mf][nf][2], acc[mf][nf][3]);
        }
    }
}

extern "C" void kernel_launch(void* const* d_in, const int* in_sizes, int n_in,
                              void* d_out, int out_size)
{
    const float* feat   = (const float*)d_in[0];   // [47820, 1024] fp32
    const float* weight = (const float*)d_in[1];   // [1024, 4096] fp32
    float* out = (float*)d_out;                    // [11955, 1024] fp32
    (void)in_sizes; (void)n_in; (void)out_size;

    cudaFuncSetAttribute(merger_gemm, cudaFuncAttributeMaxDynamicSharedMemorySize, SMEM_DYN);
    reorder_w_kernel<<<4096, 256>>>(weight);
    merger_gemm<<<dim3(8, 94), 128, SMEM_DYN>>>(feat, out);
}

// round 7
// speedup vs baseline: 2.6334x; 1.0209x over previous
#include <cuda_runtime.h>
#include <cstdint>

// ---------------------------------------------------------------------------
// LightOnOCR patch merger: fused 2x2 unfold gather + Linear(4096->1024), TF32
// mma.sync. M=11955, N=1024, K=4096. CTA 128x128, 4 warps (64x64 each),
// K-chunk 32, 3-stage cp.async pipeline (96KB -> 2 CTAs/SM), XOR-swizzled
// smem, coalesced fills. A fed as raw f32 bits (HW tf32 truncation); B RNA.
// ---------------------------------------------------------------------------

#define M_TOTAL 11955
#define STAGE_BYTES 32768            // A 16KB (128 rows x 128B) + B 16KB
#define SMEM_DYN (3 * STAGE_BYTES)   // 98304 B -> 2 CTAs/SM

static __device__ unsigned g_Wr[4u * 1024u * 1024u];   // [off][n][dd], tf32 bits (RNA)

// Image table (IMAGE_SIZES, PATCH=14, MERGE=2)
__constant__ int c_moff[7] = {0, 2420, 4620, 6060, 9085, 10525, 11955};
__constant__ int c_toff[6] = {0, 9680, 18480, 24240, 36340, 42100};
__constant__ int c_wm[6]   = {44, 55, 45, 55, 32, 55};
__constant__ int c_w[6]    = {88, 110, 90, 110, 64, 110};

__device__ __forceinline__ unsigned f2tf(float f) {
    unsigned u;
    asm("cvt.rna.tf32.f32 %0, %1;" : "=r"(u) : "f"(f));
    return u;
}
__device__ __forceinline__ uint32_t s2u(const void* p) {
    uint32_t a;
    asm("{ .reg .u64 t; cvta.to.shared.u64 t, %1; cvt.u32.u64 %0, t; }" : "=r"(a) : "l"(p));
    return a;
}
__device__ __forceinline__ void cp16(uint32_t dst, const void* src) {
    asm volatile("cp.async.cg.shared.global [%0], [%1], 16;" :: "r"(dst), "l"(src) : "memory");
}

// Weight reorder: [1024, 4096] -> g_Wr[off][n][dd], tf32-rounded (RNA).
__global__ void reorder_w_kernel(const float* __restrict__ w) {
    int id = blockIdx.x * 256 + threadIdx.x;
    int n = id >> 10, dd = id & 1023;
    float4 v = *reinterpret_cast<const float4*>(w + (size_t)n * 4096 + (dd << 2));
    g_Wr[0u * 1048576u + (n << 10) + dd] = f2tf(v.x);
    g_Wr[1u * 1048576u + (n << 10) + dd] = f2tf(v.y);
    g_Wr[2u * 1048576u + (n << 10) + dd] = f2tf(v.z);
    g_Wr[3u * 1048576u + (n << 10) + dd] = f2tf(v.w);
}

__global__ __launch_bounds__(128, 2) void merger_gemm(
    const float* __restrict__ feat, float* __restrict__ out)
{
    extern __shared__ char smem[];
    __shared__ int sTok[128], sWd[128];
    const int t = threadIdx.x, wid = t >> 5, lane = t & 31;
    const int m0 = blockIdx.y << 7, n0 = blockIdx.x << 7;

    // Row map: merged row (m0+i) -> (base token, patch width)
    {
        int r = m0 + t;
        if (r > M_TOTAL - 1) r = M_TOTAL - 1;   // clamp loads; stores guarded
        int img = 0;
        #pragma unroll
        for (int i = 1; i < 6; i++) img += (r >= c_moff[i]);
        int local = r - c_moff[img];
        int wm = c_wm[img];
        int br = local / wm, bc = local - br * wm;
        sTok[t] = c_toff[img] + (br << 1) * c_w[img] + (bc << 1);
        sWd[t]  = c_w[img];
    }
    __syncthreads();

    // Fill mapping: thread handles rows {16j + (t>>3)}, chunk c = t&7 (16B).
    // One warp covers 4 rows x 8 chunks = four full 128B lines (coalesced).
    const int rbase = t >> 3, c = t & 7;
    const uint32_t csw = (uint32_t)(c ^ (rbase & 7)) << 4;
    const uint32_t off0 = (uint32_t)rbase * 128 + csw;
    int tokA[8], wdA[8];
    const unsigned* pB[8];
    #pragma unroll
    for (int j = 0; j < 8; j++) {
        int row = (j << 4) + rbase;
        tokA[j] = sTok[row];
        wdA[j]  = sWd[row];
        pB[j]   = g_Wr + ((size_t)(n0 + row) << 10) + (c << 2);
    }
    const uint32_t sbase = s2u(smem);

    auto fill = [&](int kc) {
        const int s = kc % 3;
        const int koff = kc >> 5;
        const int dd0 = (kc & 31) << 5;
        const int kh = koff >> 1, kw = koff & 1;
        const uint32_t dA = sbase + s * STAGE_BYTES + off0;
        const size_t woff = ((size_t)koff << 20) + dd0;
        const size_t aoff = dd0 + (c << 2);
        #pragma unroll
        for (int j = 0; j < 8; j++) {
            int token = tokA[j] + kh * wdA[j] + kw;
            cp16(dA + (j << 11), feat + (size_t)token * 1024 + aoff);
            cp16(dA + 16384 + (j << 11), pB[j] + woff);
        }
        asm volatile("cp.async.commit_group;" ::: "memory");
    };

    const int tg = lane >> 2, t4 = lane & 3;
    const int wr = wid >> 1, wc = wid & 1;      // warp grid 2x2, 64x64 tiles

    float acc[4][8][4];
    #pragma unroll
    for (int mf = 0; mf < 4; mf++)
        #pragma unroll
        for (int nf = 0; nf < 8; nf++)
            #pragma unroll
            for (int i = 0; i < 4; i++) acc[mf][nf][i] = 0.0f;

    fill(0); fill(1);

    for (int kt = 0; kt < 128; kt++) {
        if (kt < 127) asm volatile("cp.async.wait_group 1;" ::: "memory");
        else          asm volatile("cp.async.wait_group 0;" ::: "memory");
        __syncthreads();
        if (kt + 2 < 128) fill(kt + 2);

        const unsigned* sA = reinterpret_cast<const unsigned*>(smem + (kt % 3) * STAGE_BYTES);
        const unsigned* sB = sA + 4096;
        #pragma unroll
        for (int ks = 0; ks < 4; ks++) {
            // swizzled word offsets within a row for k = ks*8 + t4 (+4)
            const int x0 = ((((ks << 1)    ) ^ tg) << 2) + t4;
            const int x1 = ((((ks << 1) + 1) ^ tg) << 2) + t4;
            unsigned a[4][4];
            #pragma unroll
            for (int mf = 0; mf < 4; mf++) {
                const int mrow = (wr << 6) + (mf << 4) + tg;
                const unsigned* p0 = sA + (mrow << 5);
                const unsigned* p8 = p0 + 256;
                a[mf][0] = p0[x0];            // raw f32 bits: HW tf32 truncation
                a[mf][1] = p8[x0];
                a[mf][2] = p0[x1];
                a[mf][3] = p8[x1];
            }
            #pragma unroll
            for (int nf = 0; nf < 8; nf++) {
                const int nrow = (wc << 6) + (nf << 3) + tg;
                const unsigned* q = sB + (nrow << 5);
                unsigned b0 = q[x0];
                unsigned b1 = q[x1];
                #pragma unroll
                for (int mf = 0; mf < 4; mf++) {
                    asm volatile(
                        "mma.sync.aligned.m16n8k8.row.col.f32.tf32.tf32.f32 "
                        "{%0,%1,%2,%3}, {%4,%5,%6,%7}, {%8,%9}, {%0,%1,%2,%3};"
                        : "+f"(acc[mf][nf][0]), "+f"(acc[mf][nf][1]),
                          "+f"(acc[mf][nf][2]), "+f"(acc[mf][nf][3])
                        : "r"(a[mf][0]), "r"(a[mf][1]), "r"(a[mf][2]), "r"(a[mf][3]),
                          "r"(b0), "r"(b1));
                }
            }
        }
    }

    // Epilogue
    #pragma unroll
    for (int mf = 0; mf < 4; mf++) {
        const int row0 = m0 + (wr << 6) + (mf << 4) + tg;
        #pragma unroll
        for (int nf = 0; nf < 8; nf++) {
            const int col = n0 + (wc << 6) + (nf << 3) + (t4 << 1);
            if (row0 < M_TOTAL)
                *reinterpret_cast<float2*>(out + (size_t)row0 * 1024 + col) =
                    make_float2(acc[mf][nf][0], acc[mf][nf][1]);
            if (row0 + 8 < M_TOTAL)
                *reinterpret_cast<float2*>(out + (size_t)(row0 + 8) * 1024 + col) =
                    make_float2(acc[mf][nf][2], acc[mf][nf][3]);
        }
    }
}

extern "C" void kernel_launch(void* const* d_in, const int* in_sizes, int n_in,
                              void* d_out, int out_size)
{
    const float* feat   = (const float*)d_in[0];   // [47820, 1024] fp32
    const float* weight = (const float*)d_in[1];   // [1024, 4096] fp32
    float* out = (float*)d_out;                    // [11955, 1024] fp32
    (void)in_sizes; (void)n_in; (void)out_size;

    cudaFuncSetAttribute(merger_gemm, cudaFuncAttributeMaxDynamicSharedMemorySize, SMEM_DYN);
    reorder_w_kernel<<<4096, 256>>>(weight);
    merger_gemm<<<dim3(8, 94), 128, SMEM_DYN>>>(feat, out);
}